// round 7
// baseline (speedup 1.0000x reference)
#include <cuda_runtime.h>
#include <cuda_bf16.h>
#include <math.h>
#include <stdint.h>

#define BSZ 256
#define N0 1024
#define N1 2048
#define N2 1024
#define N3 512
#define TT 16
#define KC 320   // Eigen MT gebp depth-blocking (cap 320, multiple of 8)

// ------------------------- device scratch (static) -------------------------
__device__ __align__(16) float g_I0[BSZ * N1];   // inputs @ w0^T (time-invariant)
__device__ __align__(16) float g_p1[BSZ * N2];
__device__ __align__(16) float g_p2[BSZ * N3];
__device__ __align__(16) float g_s0[BSZ * N1];
__device__ __align__(16) float g_s1[BSZ * N2];
__device__ __align__(16) float g_V0[BSZ * N1], g_L0[BSZ * N1];
__device__ __align__(16) float g_V1[BSZ * N2], g_L1[BSZ * N2];
__device__ __align__(16) float g_V2[BSZ * N3], g_L2[BSZ * N3];
__device__ float g_wn0[N1], g_wn1[N2], g_wn2[N3];
__device__ double g_cost;
__device__ unsigned int g_tot;

// ------------------------------- init --------------------------------------
__global__ void init_k() {
    int i = blockIdx.x * 256 + threadIdx.x;
    if (i < BSZ * N1) { g_V0[i] = 0.f; g_L0[i] = -1e9f; }
    if (i < BSZ * N2) { g_V1[i] = 0.f; g_L1[i] = -1e9f; }
    if (i < BSZ * N3) { g_V2[i] = 0.f; g_L2[i] = -1e9f; }
    if (i == 0) { g_cost = 0.0; g_tot = 0u; }
}

// ---- per-row weight norms: strict sequential ascending-k FMA chain --------
__global__ void wnorm_k(const float* __restrict__ w, int K, int Nrows,
                        float* __restrict__ o) {
    int row = blockIdx.x * 128 + threadIdx.x;
    if (row >= Nrows) return;
    const float* wr = w + (size_t)row * K;
    float s = 0.f;
    for (int j = 0; j < K; j++) {
        float v = __ldg(&wr[j]);
        s = __fmaf_rn(v, v, s);
    }
    o[row] = sqrtf(s);
}

// ------------------------------- GEMM ---------------------------------------
// Eigen-gebp-ordered fp32: per output, ascending-k FMA chain WITHIN each
// kc=320 panel (fresh accumulator per panel), panels combined ascending:
//   C = ((p0 + p1) + p2) + ...
// A:[256,K], B:[N,K] row-major. Tile 64m x 32n x 16k, 128 threads, rf 8x2.
__global__ void __launch_bounds__(128) gemm_k(const float* __restrict__ A,
                                              const float* __restrict__ Bm,
                                              float* __restrict__ C,
                                              int N, int K) {
    __shared__ float As[16][68];
    __shared__ float Bs[16][36];
    const int bn0 = blockIdx.x * 32, bm0 = blockIdx.y * 64;
    const int tid = threadIdx.x;
    const int tx = tid & 15, ty = tid >> 4;      // n-group 0..15, m-group 0..7
    const float* Ag = A + (size_t)bm0 * K;
    const float* Bg = Bm + (size_t)bn0 * K;

    float acc[8][2];   // current panel partial
    float tot[8][2];   // running combined sum
    #pragma unroll
    for (int i = 0; i < 8; i++) {
        acc[i][0] = 0.f; acc[i][1] = 0.f;
        tot[i][0] = 0.f; tot[i][1] = 0.f;
    }

    for (int kt = 0; kt < K; kt += 16) {
        {   // A tile: 64 rows x 16 k = 256 float4; 2 per thread
            #pragma unroll
            for (int i = 0; i < 2; i++) {
                int id = tid + i * 128;
                int row = id >> 2, kq = (id & 3) * 4;
                float4 va = *(const float4*)(Ag + (size_t)row * K + kt + kq);
                As[kq + 0][row] = va.x; As[kq + 1][row] = va.y;
                As[kq + 2][row] = va.z; As[kq + 3][row] = va.w;
            }
            // B tile: 32 rows x 16 k = 128 float4; 1 per thread
            int row = tid >> 2, kq = (tid & 3) * 4;
            float4 vb = *(const float4*)(Bg + (size_t)row * K + kt + kq);
            Bs[kq + 0][row] = vb.x; Bs[kq + 1][row] = vb.y;
            Bs[kq + 2][row] = vb.z; Bs[kq + 3][row] = vb.w;
        }
        __syncthreads();
        #pragma unroll
        for (int k = 0; k < 16; k++) {
            float4 a0 = *(const float4*)&As[k][ty * 8];
            float4 a1 = *(const float4*)&As[k][ty * 8 + 4];
            float b0 = Bs[k][tx * 2], b1 = Bs[k][tx * 2 + 1];
            float av[8] = {a0.x, a0.y, a0.z, a0.w, a1.x, a1.y, a1.z, a1.w};
            #pragma unroll
            for (int i = 0; i < 8; i++) {
                acc[i][0] = __fmaf_rn(av[i], b0, acc[i][0]);
                acc[i][1] = __fmaf_rn(av[i], b1, acc[i][1]);
            }
        }
        __syncthreads();
        // Panel boundary (k multiple of KC=320; 320%16==0) or end of K:
        int ke = kt + 16;
        if ((ke % KC) == 0 || ke == K) {
            #pragma unroll
            for (int i = 0; i < 8; i++) {
                tot[i][0] = __fadd_rn(tot[i][0], acc[i][0]);
                tot[i][1] = __fadd_rn(tot[i][1], acc[i][1]);
                acc[i][0] = 0.f; acc[i][1] = 0.f;
            }
        }
    }
    float* Cg = C + (size_t)bm0 * N + bn0;
    #pragma unroll
    for (int i = 0; i < 8; i++) {
        float2 v = make_float2(tot[i][0], tot[i][1]);
        *(float2*)&Cg[(size_t)(ty * 8 + i) * N + tx * 2] = v;
    }
}

// ------------------------------- LIF step ----------------------------------
__global__ void lif_k(const float* __restrict__ cur_in,
                      const float* __restrict__ cn, const float* __restrict__ tn,
                      const float* __restrict__ th, const float* __restrict__ wn,
                      float* __restrict__ V, float* __restrict__ Ls,
                      float* __restrict__ sout, float* __restrict__ odst,
                      int N, float t, float costfac) {
    int i = blockIdx.x * 256 + threadIdx.x;
    int n = i % N;
    float wnv = wn[n];
    float sc    = __fmul_rn(0.05f, wnv);
    float cur   = __fmaf_rn(cn[i], sc, cur_in[i]);
    float ls = Ls[i];
    float Vold = V[i];
    bool refrac = __fadd_rn(t, -ls) < 2.0f;
    float Vcand = __fmaf_rn(0.95f, Vold, cur);
    float Vn = refrac ? Vold : Vcand;
    float thr = __fmaf_rn(tn[i], 0.1f, th[n]);
    bool sp = (!refrac) && (Vn > thr);
    V[i] = sp ? 0.f : Vn;
    Ls[i] = sp ? t : ls;
    float spf = sp ? 1.f : 0.f;
    if (sout) sout[i] = spf;
    if (odst) odst[i] = spf;

    float c = sp ? __fmul_rn(costfac, wnv) : 0.f;
    unsigned int scnt = sp ? 1u : 0u;
    #pragma unroll
    for (int off = 16; off; off >>= 1) {
        c += __shfl_down_sync(0xffffffffu, c, off);
        scnt += __shfl_down_sync(0xffffffffu, scnt, off);
    }
    __shared__ float shc[8];
    __shared__ unsigned int shs[8];
    if ((threadIdx.x & 31) == 0) { shc[threadIdx.x >> 5] = c; shs[threadIdx.x >> 5] = scnt; }
    __syncthreads();
    if (threadIdx.x == 0) {
        float tc = 0.f; unsigned int ts = 0u;
        #pragma unroll
        for (int k = 0; k < 8; k++) { tc += shc[k]; ts += shs[k]; }
        atomicAdd(&g_cost, (double)tc);
        atomicAdd(&g_tot, ts);
    }
}

// ------------------------------- finalize -----------------------------------
__global__ void final_k(float* out, int out_size) {
    float cost = (float)g_cost;
    float p1 = __fdiv_rn((float)g_tot, 14680064.f);
    float p0 = __fadd_rn(1.f, -p1);
    float ent = -(p1 * log2f(p1 + 1e-12f) + p0 * log2f(p0 + 1e-12f));
    if (out_size >= BSZ * N3 + 2) {
        out[BSZ * N3] = cost;
        out[BSZ * N3 + 1] = ent;
    } else if (out_size >= 2) {
        out[out_size - 2] = cost;
        out[out_size - 1] = ent;
    }
}

// ------------------------------- launch -------------------------------------
extern "C" void kernel_launch(void* const* d_in, const int* in_sizes, int n_in,
                              void* d_out, int out_size) {
    const float *inputs, *w0, *w1, *w2, *th0, *th1, *th2;
    const float *cn0, *cn1, *cn2, *tn0, *tn1, *tn2;
    inputs = (const float*)d_in[0];
    if (in_sizes[2] == 2048) {
        // interleaved (setup_inputs dict order): w0,th0,cn0,tn0, w1,th1,cn1,tn1, ...
        w0 = (const float*)d_in[1];  th0 = (const float*)d_in[2];
        cn0 = (const float*)d_in[3]; tn0 = (const float*)d_in[4];
        w1 = (const float*)d_in[5];  th1 = (const float*)d_in[6];
        cn1 = (const float*)d_in[7]; tn1 = (const float*)d_in[8];
        w2 = (const float*)d_in[9];  th2 = (const float*)d_in[10];
        cn2 = (const float*)d_in[11]; tn2 = (const float*)d_in[12];
    } else {
        // grouped (reference signature order)
        w0 = (const float*)d_in[1];  w1 = (const float*)d_in[2];  w2 = (const float*)d_in[3];
        th0 = (const float*)d_in[4]; th1 = (const float*)d_in[5]; th2 = (const float*)d_in[6];
        cn0 = (const float*)d_in[7]; cn1 = (const float*)d_in[8]; cn2 = (const float*)d_in[9];
        tn0 = (const float*)d_in[10]; tn1 = (const float*)d_in[11]; tn2 = (const float*)d_in[12];
    }
    float* out = (float*)d_out;

    void *pI0, *pp1, *pp2, *ps0, *ps1, *pV0, *pV1, *pV2, *pL0, *pL1, *pL2,
         *pwn0, *pwn1, *pwn2;
    cudaGetSymbolAddress(&pI0, g_I0);
    cudaGetSymbolAddress(&pp1, g_p1);
    cudaGetSymbolAddress(&pp2, g_p2);
    cudaGetSymbolAddress(&ps0, g_s0);
    cudaGetSymbolAddress(&ps1, g_s1);
    cudaGetSymbolAddress(&pV0, g_V0);
    cudaGetSymbolAddress(&pV1, g_V1);
    cudaGetSymbolAddress(&pV2, g_V2);
    cudaGetSymbolAddress(&pL0, g_L0);
    cudaGetSymbolAddress(&pL1, g_L1);
    cudaGetSymbolAddress(&pL2, g_L2);
    cudaGetSymbolAddress(&pwn0, g_wn0);
    cudaGetSymbolAddress(&pwn1, g_wn1);
    cudaGetSymbolAddress(&pwn2, g_wn2);

    init_k<<<2048, 256>>>();
    wnorm_k<<<(N1 + 127) / 128, 128>>>(w0, N0, N1, (float*)pwn0);
    wnorm_k<<<(N2 + 127) / 128, 128>>>(w1, N1, N2, (float*)pwn1);
    wnorm_k<<<(N3 + 127) / 128, 128>>>(w2, N2, N3, (float*)pwn2);

    // time-invariant input current: I0 = inputs @ w0^T
    gemm_k<<<dim3(N1 / 32, BSZ / 64, 1), 128>>>(inputs, w0, (float*)pI0, N1, N0);

    for (int t = 1; t <= TT; t++) {
        float tf = (float)t;
        float cf = 0.01f * fminf(10.f, 17.f - tf);
        size_t o0 = (size_t)(t - 1) * BSZ * N1;
        size_t o1 = (size_t)(t - 1) * BSZ * N2;
        size_t o2 = (size_t)(t - 1) * BSZ * N3;

        lif_k<<<BSZ * N1 / 256, 256>>>((const float*)pI0, cn0 + o0, tn0 + o0,
                                       th0, (const float*)pwn0, (float*)pV0,
                                       (float*)pL0, (float*)ps0, nullptr, N1, tf, cf);
        gemm_k<<<dim3(N2 / 32, BSZ / 64, 1), 128>>>((const float*)ps0, w1,
                                                    (float*)pp1, N2, N1);
        lif_k<<<BSZ * N2 / 256, 256>>>((const float*)pp1, cn1 + o1, tn1 + o1,
                                       th1, (const float*)pwn1, (float*)pV1,
                                       (float*)pL1, (float*)ps1, nullptr, N2, tf, cf);
        gemm_k<<<dim3(N3 / 32, BSZ / 64, 1), 128>>>((const float*)ps1, w2,
                                                    (float*)pp2, N3, N2);
        lif_k<<<BSZ * N3 / 256, 256>>>((const float*)pp2, cn2 + o2, tn2 + o2,
                                       th2, (const float*)pwn2, (float*)pV2,
                                       (float*)pL2, nullptr,
                                       (t == TT) ? out : nullptr, N3, tf, cf);
    }
    final_k<<<1, 1>>>(out, out_size);
}

// round 8
// speedup vs baseline: 1.4274x; 1.4274x over previous
#include <cuda_runtime.h>
#include <cuda_bf16.h>
#include <math.h>
#include <stdint.h>

#define BSZ 256
#define N0 1024
#define N1 2048
#define N2 1024
#define N3 512
#define TT 16
#define KC 320   // Eigen MT gebp depth-blocking (validated bit-exact in R7)

// ------------------------- device scratch (static) -------------------------
__device__ __align__(16) float g_I0p[4 * BSZ * N1];  // I0 panel partials
__device__ __align__(16) float g_I0[BSZ * N1];       // combined I0
__device__ __align__(16) float g_p1[7 * BSZ * N2];   // layer1 panel partials
__device__ __align__(16) float g_p2[4 * BSZ * N3];   // layer2 panel partials
__device__ __align__(16) float g_s0[BSZ * N1];
__device__ __align__(16) float g_s1[BSZ * N2];
__device__ __align__(16) float g_V0[BSZ * N1], g_L0[BSZ * N1];
__device__ __align__(16) float g_V1[BSZ * N2], g_L1[BSZ * N2];
__device__ __align__(16) float g_V2[BSZ * N3], g_L2[BSZ * N3];
__device__ float g_wn0[N1], g_wn1[N2], g_wn2[N3];
__device__ double g_cost;
__device__ unsigned int g_tot;

// ------------------------- f32x2 packed helpers ----------------------------
__device__ __forceinline__ unsigned long long f2pack(float x, float y) {
    unsigned long long r;
    asm("mov.b64 %0, {%1, %2};" : "=l"(r) : "f"(x), "f"(y));
    return r;
}
__device__ __forceinline__ void f2fma(unsigned long long& d,
                                      unsigned long long a, unsigned long long b) {
    asm("fma.rn.f32x2 %0, %1, %2, %0;" : "+l"(d) : "l"(a), "l"(b));
}
__device__ __forceinline__ void f2unpack(float& x, float& y, unsigned long long v) {
    asm("mov.b64 {%0, %1}, %2;" : "=f"(x), "=f"(y) : "l"(v));
}

// ------------------------------- init --------------------------------------
__global__ void init_k() {
    int i = blockIdx.x * 256 + threadIdx.x;
    if (i < BSZ * N1) { g_V0[i] = 0.f; g_L0[i] = -1e9f; }
    if (i < BSZ * N2) { g_V1[i] = 0.f; g_L1[i] = -1e9f; }
    if (i < BSZ * N3) { g_V2[i] = 0.f; g_L2[i] = -1e9f; }
    if (i == 0) { g_cost = 0.0; g_tot = 0u; }
}

// ---- per-row weight norms: warp per row, coalesced, tree reduce ------------
// (wnorm order proven bit-neutral for spike decisions: R3==R4==R5 outputs)
__global__ void wnorm_k(const float* __restrict__ w, int K, int Nrows,
                        float* __restrict__ o) {
    int row = blockIdx.x * 8 + (threadIdx.x >> 5);
    int lane = threadIdx.x & 31;
    if (row >= Nrows) return;
    const float* wr = w + (size_t)row * K;
    float s = 0.f;
    for (int j = lane; j < K; j += 32) {
        float v = wr[j];
        s = __fadd_rn(s, __fmul_rn(v, v));
    }
    #pragma unroll
    for (int off = 16; off; off >>= 1)
        s = __fadd_rn(s, __shfl_down_sync(0xffffffffu, s, off));
    if (lane == 0) o[row] = sqrtf(s);
}

// ------------------------------- GEMM (one kc-panel per z) ------------------
// P[z,m,n] = strict ascending-k FMA chain over panel z (k in [z*KC, z*KC+len)).
// Packed f32x2 over adjacent m-rows: per-component rn == two scalar FFMAs.
// A:[256,K], B:[N,K] row-major. Tile 64m x 32n x 16k, 128 threads.
__global__ void __launch_bounds__(128) gemm_k(const float* __restrict__ A,
                                              const float* __restrict__ Bm,
                                              float* __restrict__ P,
                                              int N, int K) {
    __shared__ float As[16][68];
    __shared__ float Bs[16][36];
    const int bn0 = blockIdx.x * 32, bm0 = blockIdx.y * 64;
    const int k0 = blockIdx.z * KC;
    const int kchunk = min(KC, K - k0);
    const int tid = threadIdx.x;
    const int tx = tid & 15, ty = tid >> 4;      // n-group 0..15, m-group 0..7
    const float* Ag = A + (size_t)bm0 * K + k0;
    const float* Bg = Bm + (size_t)bn0 * K + k0;

    unsigned long long acc2[4][2];               // (row pair) x (2 cols)
    #pragma unroll
    for (int p = 0; p < 4; p++) { acc2[p][0] = 0ull; acc2[p][1] = 0ull; }

    for (int kt = 0; kt < kchunk; kt += 16) {
        {   // A tile: 64 rows x 16 k = 256 float4; 2 per thread
            #pragma unroll
            for (int i = 0; i < 2; i++) {
                int id = tid + i * 128;
                int row = id >> 2, kq = (id & 3) * 4;
                float4 va = *(const float4*)(Ag + (size_t)row * K + kt + kq);
                As[kq + 0][row] = va.x; As[kq + 1][row] = va.y;
                As[kq + 2][row] = va.z; As[kq + 3][row] = va.w;
            }
            // B tile: 32 rows x 16 k = 128 float4; 1 per thread
            int row = tid >> 2, kq = (tid & 3) * 4;
            float4 vb = *(const float4*)(Bg + (size_t)row * K + kt + kq);
            Bs[kq + 0][row] = vb.x; Bs[kq + 1][row] = vb.y;
            Bs[kq + 2][row] = vb.z; Bs[kq + 3][row] = vb.w;
        }
        __syncthreads();
        #pragma unroll
        for (int k = 0; k < 16; k++) {
            const ulonglong2* ap = (const ulonglong2*)&As[k][ty * 8];
            ulonglong2 a01 = ap[0];
            ulonglong2 a23 = ap[1];
            float2 b = *(const float2*)&Bs[k][tx * 2];
            unsigned long long bb0 = f2pack(b.x, b.x);
            unsigned long long bb1 = f2pack(b.y, b.y);
            f2fma(acc2[0][0], a01.x, bb0); f2fma(acc2[0][1], a01.x, bb1);
            f2fma(acc2[1][0], a01.y, bb0); f2fma(acc2[1][1], a01.y, bb1);
            f2fma(acc2[2][0], a23.x, bb0); f2fma(acc2[2][1], a23.x, bb1);
            f2fma(acc2[3][0], a23.y, bb0); f2fma(acc2[3][1], a23.y, bb1);
        }
        __syncthreads();
    }
    float* Pg = P + (size_t)blockIdx.z * BSZ * N + (size_t)bm0 * N + bn0;
    #pragma unroll
    for (int p = 0; p < 4; p++) {
        float r0c0, r1c0, r0c1, r1c1;
        f2unpack(r0c0, r1c0, acc2[p][0]);
        f2unpack(r0c1, r1c1, acc2[p][1]);
        *(float2*)&Pg[(size_t)(ty * 8 + 2 * p) * N + tx * 2] =
            make_float2(r0c0, r0c1);
        *(float2*)&Pg[(size_t)(ty * 8 + 2 * p + 1) * N + tx * 2] =
            make_float2(r1c0, r1c1);
    }
}

// ---- combine I0 panels once (ordered, starts from 0 like R7's tot) ---------
__global__ void comb_k(const float* __restrict__ P, float* __restrict__ O,
                       int n, int S) {
    int i = blockIdx.x * 256 + threadIdx.x;
    if (i >= n) return;
    float t = 0.f;
    for (int s = 0; s < S; s++) t = __fadd_rn(t, P[(size_t)s * n + i]);
    O[i] = t;
}

// ------------------------------- LIF step ----------------------------------
// Combines S panel partials in ascending order (fadd chain from 0 — bitwise
// identical to R7's in-register tot), then LIF dynamics.
__global__ void lif_k(const float* __restrict__ part, int S,
                      const float* __restrict__ cn, const float* __restrict__ tn,
                      const float* __restrict__ th, const float* __restrict__ wn,
                      float* __restrict__ V, float* __restrict__ Ls,
                      float* __restrict__ sout, float* __restrict__ odst,
                      int N, float t, float costfac) {
    int i = blockIdx.x * 256 + threadIdx.x;
    int n = i % N;
    size_t sz = (size_t)BSZ * N;
    float cur;
    if (S == 1) {
        cur = part[i];
    } else {
        cur = __fadd_rn(0.f, part[i]);
        for (int s = 1; s < S; s++) cur = __fadd_rn(cur, part[(size_t)s * sz + i]);
    }
    float wnv = wn[n];
    float sc  = __fmul_rn(0.05f, wnv);
    cur = __fmaf_rn(cn[i], sc, cur);
    float ls = Ls[i];
    float Vold = V[i];
    bool refrac = __fadd_rn(t, -ls) < 2.0f;
    float Vcand = __fmaf_rn(0.95f, Vold, cur);
    float Vn = refrac ? Vold : Vcand;
    float thr = __fmaf_rn(tn[i], 0.1f, th[n]);
    bool sp = (!refrac) && (Vn > thr);
    V[i] = sp ? 0.f : Vn;
    Ls[i] = sp ? t : ls;
    float spf = sp ? 1.f : 0.f;
    if (sout) sout[i] = spf;
    if (odst) odst[i] = spf;

    float c = sp ? __fmul_rn(costfac, wnv) : 0.f;
    unsigned int scnt = sp ? 1u : 0u;
    #pragma unroll
    for (int off = 16; off; off >>= 1) {
        c += __shfl_down_sync(0xffffffffu, c, off);
        scnt += __shfl_down_sync(0xffffffffu, scnt, off);
    }
    __shared__ float shc[8];
    __shared__ unsigned int shs[8];
    if ((threadIdx.x & 31) == 0) { shc[threadIdx.x >> 5] = c; shs[threadIdx.x >> 5] = scnt; }
    __syncthreads();
    if (threadIdx.x == 0) {
        float tc = 0.f; unsigned int ts = 0u;
        #pragma unroll
        for (int k = 0; k < 8; k++) { tc += shc[k]; ts += shs[k]; }
        atomicAdd(&g_cost, (double)tc);
        atomicAdd(&g_tot, ts);
    }
}

// ------------------------------- finalize -----------------------------------
__global__ void final_k(float* out, int out_size) {
    float cost = (float)g_cost;
    float p1 = __fdiv_rn((float)g_tot, 14680064.f);
    float p0 = __fadd_rn(1.f, -p1);
    float ent = -(p1 * log2f(p1 + 1e-12f) + p0 * log2f(p0 + 1e-12f));
    if (out_size >= BSZ * N3 + 2) {
        out[BSZ * N3] = cost;
        out[BSZ * N3 + 1] = ent;
    } else if (out_size >= 2) {
        out[out_size - 2] = cost;
        out[out_size - 1] = ent;
    }
}

// ------------------------------- launch -------------------------------------
extern "C" void kernel_launch(void* const* d_in, const int* in_sizes, int n_in,
                              void* d_out, int out_size) {
    const float *inputs, *w0, *w1, *w2, *th0, *th1, *th2;
    const float *cn0, *cn1, *cn2, *tn0, *tn1, *tn2;
    inputs = (const float*)d_in[0];
    if (in_sizes[2] == 2048) {
        // interleaved (setup_inputs dict order)
        w0 = (const float*)d_in[1];  th0 = (const float*)d_in[2];
        cn0 = (const float*)d_in[3]; tn0 = (const float*)d_in[4];
        w1 = (const float*)d_in[5];  th1 = (const float*)d_in[6];
        cn1 = (const float*)d_in[7]; tn1 = (const float*)d_in[8];
        w2 = (const float*)d_in[9];  th2 = (const float*)d_in[10];
        cn2 = (const float*)d_in[11]; tn2 = (const float*)d_in[12];
    } else {
        w0 = (const float*)d_in[1];  w1 = (const float*)d_in[2];  w2 = (const float*)d_in[3];
        th0 = (const float*)d_in[4]; th1 = (const float*)d_in[5]; th2 = (const float*)d_in[6];
        cn0 = (const float*)d_in[7]; cn1 = (const float*)d_in[8]; cn2 = (const float*)d_in[9];
        tn0 = (const float*)d_in[10]; tn1 = (const float*)d_in[11]; tn2 = (const float*)d_in[12];
    }
    float* out = (float*)d_out;

    void *pI0p, *pI0, *pp1, *pp2, *ps0, *ps1, *pV0, *pV1, *pV2,
         *pL0, *pL1, *pL2, *pwn0, *pwn1, *pwn2;
    cudaGetSymbolAddress(&pI0p, g_I0p);
    cudaGetSymbolAddress(&pI0, g_I0);
    cudaGetSymbolAddress(&pp1, g_p1);
    cudaGetSymbolAddress(&pp2, g_p2);
    cudaGetSymbolAddress(&ps0, g_s0);
    cudaGetSymbolAddress(&ps1, g_s1);
    cudaGetSymbolAddress(&pV0, g_V0);
    cudaGetSymbolAddress(&pV1, g_V1);
    cudaGetSymbolAddress(&pV2, g_V2);
    cudaGetSymbolAddress(&pL0, g_L0);
    cudaGetSymbolAddress(&pL1, g_L1);
    cudaGetSymbolAddress(&pL2, g_L2);
    cudaGetSymbolAddress(&pwn0, g_wn0);
    cudaGetSymbolAddress(&pwn1, g_wn1);
    cudaGetSymbolAddress(&pwn2, g_wn2);

    const int NP1 = (N0 + KC - 1) / KC;  // 4 panels for K=1024
    const int NP2 = (N1 + KC - 1) / KC;  // 7 panels for K=2048

    init_k<<<2048, 256>>>();
    wnorm_k<<<N1 / 8, 256>>>(w0, N0, N1, (float*)pwn0);
    wnorm_k<<<N2 / 8, 256>>>(w1, N1, N2, (float*)pwn1);
    wnorm_k<<<N3 / 8, 256>>>(w2, N2, N3, (float*)pwn2);

    // time-invariant input current: I0 = inputs @ w0^T (panel-parallel + combine)
    gemm_k<<<dim3(N1 / 32, BSZ / 64, NP1), 128>>>(inputs, w0, (float*)pI0p, N1, N0);
    comb_k<<<BSZ * N1 / 256, 256>>>((const float*)pI0p, (float*)pI0, BSZ * N1, NP1);

    for (int t = 1; t <= TT; t++) {
        float tf = (float)t;
        float cf = 0.01f * fminf(10.f, 17.f - tf);
        size_t o0 = (size_t)(t - 1) * BSZ * N1;
        size_t o1 = (size_t)(t - 1) * BSZ * N2;
        size_t o2 = (size_t)(t - 1) * BSZ * N3;

        lif_k<<<BSZ * N1 / 256, 256>>>((const float*)pI0, 1, cn0 + o0, tn0 + o0,
                                       th0, (const float*)pwn0, (float*)pV0,
                                       (float*)pL0, (float*)ps0, nullptr, N1, tf, cf);
        gemm_k<<<dim3(N2 / 32, BSZ / 64, NP2), 128>>>((const float*)ps0, w1,
                                                      (float*)pp1, N2, N1);
        lif_k<<<BSZ * N2 / 256, 256>>>((const float*)pp1, NP2, cn1 + o1, tn1 + o1,
                                       th1, (const float*)pwn1, (float*)pV1,
                                       (float*)pL1, (float*)ps1, nullptr, N2, tf, cf);
        gemm_k<<<dim3(N3 / 32, BSZ / 64, NP1), 128>>>((const float*)ps1, w2,
                                                      (float*)pp2, N3, N2);
        lif_k<<<BSZ * N3 / 256, 256>>>((const float*)pp2, NP1, cn2 + o2, tn2 + o2,
                                       th2, (const float*)pwn2, (float*)pV2,
                                       (float*)pL2, nullptr,
                                       (t == TT) ? out : nullptr, N3, tf, cf);
    }
    final_k<<<1, 1>>>(out, out_size);
}

// round 9
// speedup vs baseline: 2.3990x; 1.6807x over previous
#include <cuda_runtime.h>
#include <cuda_bf16.h>
#include <math.h>
#include <stdint.h>

#define BSZ 256
#define N0 1024
#define N1 2048
#define N2 1024
#define N3 512
#define TT 16
#define KC 320   // Eigen MT gebp depth-blocking (validated bit-exact in R7/R8)

// ------------------------- device scratch (static) -------------------------
__device__ __align__(16) float g_I0p[4 * BSZ * N1];  // I0 panel partials
__device__ __align__(16) float g_I0[BSZ * N1];       // combined I0
__device__ __align__(16) float g_p1[7 * BSZ * N2];   // layer1 panel partials
__device__ __align__(16) float g_p2[4 * BSZ * N3];   // layer2 panel partials
__device__ __align__(16) float g_s0[BSZ * N1];
__device__ __align__(16) float g_s1[BSZ * N2];
__device__ __align__(16) float g_V0[BSZ * N1], g_L0[BSZ * N1];
__device__ __align__(16) float g_V1[BSZ * N2], g_L1[BSZ * N2];
__device__ __align__(16) float g_V2[BSZ * N3], g_L2[BSZ * N3];
__device__ float g_wn0[N1], g_wn1[N2], g_wn2[N3];
__device__ double g_cost;
__device__ unsigned int g_tot;

// ------------------------- f32x2 packed helpers ----------------------------
__device__ __forceinline__ unsigned long long f2pack(float x, float y) {
    unsigned long long r;
    asm("mov.b64 %0, {%1, %2};" : "=l"(r) : "f"(x), "f"(y));
    return r;
}
__device__ __forceinline__ void f2fma(unsigned long long& d,
                                      unsigned long long a, unsigned long long b) {
    asm("fma.rn.f32x2 %0, %1, %2, %0;" : "+l"(d) : "l"(a), "l"(b));
}
__device__ __forceinline__ void f2unpack(float& x, float& y, unsigned long long v) {
    asm("mov.b64 {%0, %1}, %2;" : "=f"(x), "=f"(y) : "l"(v));
}

// ------------------------------- init --------------------------------------
__global__ void init_k() {
    int i = blockIdx.x * 256 + threadIdx.x;
    if (i < BSZ * N1) { g_V0[i] = 0.f; g_L0[i] = -1e9f; }
    if (i < BSZ * N2) { g_V1[i] = 0.f; g_L1[i] = -1e9f; }
    if (i < BSZ * N3) { g_V2[i] = 0.f; g_L2[i] = -1e9f; }
    if (i == 0) { g_cost = 0.0; g_tot = 0u; }
}

// ---- per-row weight norms: warp per row, coalesced, tree reduce ------------
__global__ void wnorm_k(const float* __restrict__ w, int K, int Nrows,
                        float* __restrict__ o) {
    int row = blockIdx.x * 8 + (threadIdx.x >> 5);
    int lane = threadIdx.x & 31;
    if (row >= Nrows) return;
    const float* wr = w + (size_t)row * K;
    float s = 0.f;
    for (int j = lane; j < K; j += 32) {
        float v = wr[j];
        s = __fadd_rn(s, __fmul_rn(v, v));
    }
    #pragma unroll
    for (int off = 16; off; off >>= 1)
        s = __fadd_rn(s, __shfl_down_sync(0xffffffffu, s, off));
    if (lane == 0) o[row] = sqrtf(s);
}

// ------------------------------- GEMM (one kc-panel per z) ------------------
// P[z,m,n] = strict ascending-k FMA chain over panel z. Packed f32x2 over
// adjacent m-rows (bitwise == two scalar FFMAs; validated R8).
// Tile 64m x TNn x 16k, 256 threads, register double-buffered global loads.
template <int TN>
__global__ void __launch_bounds__(256) gemm_k(const float* __restrict__ A,
                                              const float* __restrict__ Bm,
                                              float* __restrict__ P,
                                              int N, int K) {
    constexpr int NG  = TN / 2;        // n-groups: 32 (TN=64) or 16 (TN=32)
    constexpr int TYN = 256 / NG;      // m-groups: 8 or 16
    constexpr int RPT = 64 / TYN;      // rows/thread: 8 or 4
    constexpr int NP  = RPT / 2;       // row pairs: 4 or 2

    __shared__ float As[16][68];
    __shared__ float Bs[16][TN + 4];

    const int bn0 = blockIdx.x * TN, bm0 = blockIdx.y * 64;
    const int k0 = blockIdx.z * KC;
    const int kchunk = min(KC, K - k0);
    const int tid = threadIdx.x;
    const int tx = tid % NG, ty = tid / NG;

    const float* Ag = A + (size_t)bm0 * K + k0;
    const float* Bg = Bm + (size_t)bn0 * K + k0;

    unsigned long long acc2[NP][2];
    #pragma unroll
    for (int p = 0; p < NP; p++) { acc2[p][0] = 0ull; acc2[p][1] = 0ull; }

    // load tasks: A 64 rows x 4 float4-chunks = 256 (one per thread);
    //             B TN rows x 4 chunks (first TN*4 threads)
    const int arow = tid >> 2, akq = (tid & 3) * 4;
    const bool bact = (TN == 64) ? true : (tid < TN * 4);

    float4 ra = *(const float4*)(Ag + (size_t)arow * K + akq);
    float4 rb = make_float4(0.f, 0.f, 0.f, 0.f);
    if (bact) rb = *(const float4*)(Bg + (size_t)arow * K + akq);

    for (int kt = 0; kt < kchunk; kt += 16) {
        As[akq + 0][arow] = ra.x; As[akq + 1][arow] = ra.y;
        As[akq + 2][arow] = ra.z; As[akq + 3][arow] = ra.w;
        if (bact) {
            Bs[akq + 0][arow] = rb.x; Bs[akq + 1][arow] = rb.y;
            Bs[akq + 2][arow] = rb.z; Bs[akq + 3][arow] = rb.w;
        }
        __syncthreads();
        int kn = kt + 16;
        if (kn < kchunk) {   // prefetch next tile during compute
            ra = *(const float4*)(Ag + (size_t)arow * K + kn + akq);
            if (bact) rb = *(const float4*)(Bg + (size_t)arow * K + kn + akq);
        }
        #pragma unroll
        for (int k = 0; k < 16; k++) {
            float2 b = *(const float2*)&Bs[k][tx * 2];
            unsigned long long bb0 = f2pack(b.x, b.x);
            unsigned long long bb1 = f2pack(b.y, b.y);
            const ulonglong2* ap = (const ulonglong2*)&As[k][ty * RPT];
            ulonglong2 a01 = ap[0];
            f2fma(acc2[0][0], a01.x, bb0); f2fma(acc2[0][1], a01.x, bb1);
            f2fma(acc2[1][0], a01.y, bb0); f2fma(acc2[1][1], a01.y, bb1);
            if (NP == 4) {
                ulonglong2 a23 = ap[1];
                f2fma(acc2[2][0], a23.x, bb0); f2fma(acc2[2][1], a23.x, bb1);
                f2fma(acc2[3][0], a23.y, bb0); f2fma(acc2[3][1], a23.y, bb1);
            }
        }
        __syncthreads();
    }
    float* Pg = P + (size_t)blockIdx.z * BSZ * N + (size_t)bm0 * N + bn0;
    #pragma unroll
    for (int p = 0; p < NP; p++) {
        float r0c0, r1c0, r0c1, r1c1;
        f2unpack(r0c0, r1c0, acc2[p][0]);
        f2unpack(r0c1, r1c1, acc2[p][1]);
        *(float2*)&Pg[(size_t)(ty * RPT + 2 * p) * N + tx * 2] =
            make_float2(r0c0, r0c1);
        *(float2*)&Pg[(size_t)(ty * RPT + 2 * p + 1) * N + tx * 2] =
            make_float2(r1c0, r1c1);
    }
}

// ---- combine I0 panels once (ordered fadd chain from 0) --------------------
__global__ void comb_k(const float* __restrict__ P, float* __restrict__ O,
                       int n, int S) {
    int i = blockIdx.x * 256 + threadIdx.x;
    if (i >= n) return;
    float t = 0.f;
    for (int s = 0; s < S; s++) t = __fadd_rn(t, P[(size_t)s * n + i]);
    O[i] = t;
}

// ------------------------------- LIF step ----------------------------------
__global__ void lif_k(const float* __restrict__ part, int S,
                      const float* __restrict__ cn, const float* __restrict__ tn,
                      const float* __restrict__ th, const float* __restrict__ wn,
                      float* __restrict__ V, float* __restrict__ Ls,
                      float* __restrict__ sout, float* __restrict__ odst,
                      int N, float t, float costfac) {
    int i = blockIdx.x * 256 + threadIdx.x;
    int n = i % N;
    size_t sz = (size_t)BSZ * N;
    float cur;
    if (S == 1) {
        cur = part[i];
    } else {
        cur = __fadd_rn(0.f, part[i]);
        for (int s = 1; s < S; s++) cur = __fadd_rn(cur, part[(size_t)s * sz + i]);
    }
    float wnv = wn[n];
    float sc  = __fmul_rn(0.05f, wnv);
    cur = __fmaf_rn(cn[i], sc, cur);
    float ls = Ls[i];
    float Vold = V[i];
    bool refrac = __fadd_rn(t, -ls) < 2.0f;
    float Vcand = __fmaf_rn(0.95f, Vold, cur);
    float Vn = refrac ? Vold : Vcand;
    float thr = __fmaf_rn(tn[i], 0.1f, th[n]);
    bool sp = (!refrac) && (Vn > thr);
    V[i] = sp ? 0.f : Vn;
    Ls[i] = sp ? t : ls;
    float spf = sp ? 1.f : 0.f;
    if (sout) sout[i] = spf;
    if (odst) odst[i] = spf;

    float c = sp ? __fmul_rn(costfac, wnv) : 0.f;
    unsigned int scnt = sp ? 1u : 0u;
    #pragma unroll
    for (int off = 16; off; off >>= 1) {
        c += __shfl_down_sync(0xffffffffu, c, off);
        scnt += __shfl_down_sync(0xffffffffu, scnt, off);
    }
    __shared__ float shc[8];
    __shared__ unsigned int shs[8];
    if ((threadIdx.x & 31) == 0) { shc[threadIdx.x >> 5] = c; shs[threadIdx.x >> 5] = scnt; }
    __syncthreads();
    if (threadIdx.x == 0) {
        float tc = 0.f; unsigned int ts = 0u;
        #pragma unroll
        for (int k = 0; k < 8; k++) { tc += shc[k]; ts += shs[k]; }
        atomicAdd(&g_cost, (double)tc);
        atomicAdd(&g_tot, ts);
    }
}

// ------------------------------- finalize -----------------------------------
__global__ void final_k(float* out, int out_size) {
    float cost = (float)g_cost;
    float p1 = __fdiv_rn((float)g_tot, 14680064.f);
    float p0 = __fadd_rn(1.f, -p1);
    float ent = -(p1 * log2f(p1 + 1e-12f) + p0 * log2f(p0 + 1e-12f));
    if (out_size >= BSZ * N3 + 2) {
        out[BSZ * N3] = cost;
        out[BSZ * N3 + 1] = ent;
    } else if (out_size >= 2) {
        out[out_size - 2] = cost;
        out[out_size - 1] = ent;
    }
}

// ------------------------------- launch -------------------------------------
extern "C" void kernel_launch(void* const* d_in, const int* in_sizes, int n_in,
                              void* d_out, int out_size) {
    const float *inputs, *w0, *w1, *w2, *th0, *th1, *th2;
    const float *cn0, *cn1, *cn2, *tn0, *tn1, *tn2;
    inputs = (const float*)d_in[0];
    if (in_sizes[2] == 2048) {
        // interleaved (setup_inputs dict order)
        w0 = (const float*)d_in[1];  th0 = (const float*)d_in[2];
        cn0 = (const float*)d_in[3]; tn0 = (const float*)d_in[4];
        w1 = (const float*)d_in[5];  th1 = (const float*)d_in[6];
        cn1 = (const float*)d_in[7]; tn1 = (const float*)d_in[8];
        w2 = (const float*)d_in[9];  th2 = (const float*)d_in[10];
        cn2 = (const float*)d_in[11]; tn2 = (const float*)d_in[12];
    } else {
        w0 = (const float*)d_in[1];  w1 = (const float*)d_in[2];  w2 = (const float*)d_in[3];
        th0 = (const float*)d_in[4]; th1 = (const float*)d_in[5]; th2 = (const float*)d_in[6];
        cn0 = (const float*)d_in[7]; cn1 = (const float*)d_in[8]; cn2 = (const float*)d_in[9];
        tn0 = (const float*)d_in[10]; tn1 = (const float*)d_in[11]; tn2 = (const float*)d_in[12];
    }
    float* out = (float*)d_out;

    void *pI0p, *pI0, *pp1, *pp2, *ps0, *ps1, *pV0, *pV1, *pV2,
         *pL0, *pL1, *pL2, *pwn0, *pwn1, *pwn2;
    cudaGetSymbolAddress(&pI0p, g_I0p);
    cudaGetSymbolAddress(&pI0, g_I0);
    cudaGetSymbolAddress(&pp1, g_p1);
    cudaGetSymbolAddress(&pp2, g_p2);
    cudaGetSymbolAddress(&ps0, g_s0);
    cudaGetSymbolAddress(&ps1, g_s1);
    cudaGetSymbolAddress(&pV0, g_V0);
    cudaGetSymbolAddress(&pV1, g_V1);
    cudaGetSymbolAddress(&pV2, g_V2);
    cudaGetSymbolAddress(&pL0, g_L0);
    cudaGetSymbolAddress(&pL1, g_L1);
    cudaGetSymbolAddress(&pL2, g_L2);
    cudaGetSymbolAddress(&pwn0, g_wn0);
    cudaGetSymbolAddress(&pwn1, g_wn1);
    cudaGetSymbolAddress(&pwn2, g_wn2);

    const int NP1 = (N0 + KC - 1) / KC;  // 4 panels (K=1024)
    const int NP2 = (N1 + KC - 1) / KC;  // 7 panels (K=2048)

    init_k<<<2048, 256>>>();
    wnorm_k<<<N1 / 8, 256>>>(w0, N0, N1, (float*)pwn0);
    wnorm_k<<<N2 / 8, 256>>>(w1, N1, N2, (float*)pwn1);
    wnorm_k<<<N3 / 8, 256>>>(w2, N2, N3, (float*)pwn2);

    // time-invariant input current: I0 = inputs @ w0^T
    gemm_k<64><<<dim3(N1 / 64, BSZ / 64, NP1), 256>>>(inputs, w0, (float*)pI0p,
                                                      N1, N0);
    comb_k<<<BSZ * N1 / 256, 256>>>((const float*)pI0p, (float*)pI0, BSZ * N1, NP1);

    for (int t = 1; t <= TT; t++) {
        float tf = (float)t;
        float cf = 0.01f * fminf(10.f, 17.f - tf);
        size_t o0 = (size_t)(t - 1) * BSZ * N1;
        size_t o1 = (size_t)(t - 1) * BSZ * N2;
        size_t o2 = (size_t)(t - 1) * BSZ * N3;

        lif_k<<<BSZ * N1 / 256, 256>>>((const float*)pI0, 1, cn0 + o0, tn0 + o0,
                                       th0, (const float*)pwn0, (float*)pV0,
                                       (float*)pL0, (float*)ps0, nullptr, N1, tf, cf);
        gemm_k<64><<<dim3(N2 / 64, BSZ / 64, NP2), 256>>>((const float*)ps0, w1,
                                                          (float*)pp1, N2, N1);
        lif_k<<<BSZ * N2 / 256, 256>>>((const float*)pp1, NP2, cn1 + o1, tn1 + o1,
                                       th1, (const float*)pwn1, (float*)pV1,
                                       (float*)pL1, (float*)ps1, nullptr, N2, tf, cf);
        gemm_k<32><<<dim3(N3 / 32, BSZ / 64, NP1), 256>>>((const float*)ps1, w2,
                                                          (float*)pp2, N3, N2);
        lif_k<<<BSZ * N3 / 256, 256>>>((const float*)pp2, NP1, cn2 + o2, tn2 + o2,
                                       th2, (const float*)pwn2, (float*)pV2,
                                       (float*)pL2, nullptr,
                                       (t == TT) ? out : nullptr, N3, tf, cf);
    }
    final_k<<<1, 1>>>(out, out_size);
}

// round 10
// speedup vs baseline: 3.3711x; 1.4052x over previous
#include <cuda_runtime.h>
#include <cuda_bf16.h>
#include <math.h>
#include <stdint.h>

#define BSZ 256
#define N0 1024
#define N1 2048
#define N2 1024
#define N3 512
#define TT 16
#define KC 320   // Eigen MT gebp depth-blocking (validated bit-exact R7-R9)
#define MB (TT * BSZ)   // 4096 batched rows

// ------------------------- device scratch (static) -------------------------
__device__ __align__(16) float g_I0p[4 * BSZ * N1];       // I0 panel partials
__device__ __align__(16) float g_s0[MB * N1];             // spikes L0, all steps
__device__ __align__(16) float g_p1[7 * MB * N2];         // L1 panel partials
__device__ __align__(16) float g_s1[MB * N2];             // spikes L1, all steps
__device__ __align__(16) float g_p2[4 * MB * N3];         // L2 panel partials
__device__ float g_wn0[N1], g_wn1[N2], g_wn2[N3];
__device__ double g_cost;
__device__ unsigned int g_tot;

// ------------------------- f32x2 packed helpers ----------------------------
__device__ __forceinline__ unsigned long long f2pack(float x, float y) {
    unsigned long long r;
    asm("mov.b64 %0, {%1, %2};" : "=l"(r) : "f"(x), "f"(y));
    return r;
}
__device__ __forceinline__ void f2fma(unsigned long long& d,
                                      unsigned long long a, unsigned long long b) {
    asm("fma.rn.f32x2 %0, %1, %2, %0;" : "+l"(d) : "l"(a), "l"(b));
}
__device__ __forceinline__ void f2unpack(float& x, float& y, unsigned long long v) {
    asm("mov.b64 {%0, %1}, %2;" : "=f"(x), "=f"(y) : "l"(v));
}

// ------------------------------- init --------------------------------------
__global__ void init_k() {
    if (threadIdx.x == 0) { g_cost = 0.0; g_tot = 0u; }
}

// ---- per-row weight norms: warp per row, coalesced, tree reduce ------------
__global__ void wnorm_k(const float* __restrict__ w, int K, int Nrows,
                        float* __restrict__ o) {
    int row = blockIdx.x * 8 + (threadIdx.x >> 5);
    int lane = threadIdx.x & 31;
    if (row >= Nrows) return;
    const float* wr = w + (size_t)row * K;
    float s = 0.f;
    for (int j = lane; j < K; j += 32) {
        float v = wr[j];
        s = __fadd_rn(s, __fmul_rn(v, v));
    }
    #pragma unroll
    for (int off = 16; off; off >>= 1)
        s = __fadd_rn(s, __shfl_down_sync(0xffffffffu, s, off));
    if (lane == 0) o[row] = sqrtf(s);
}

// ------------------------------- GEMM (one kc-panel per z) ------------------
// P[z,m,n] = strict ascending-k FMA chain over panel z. Packed f32x2 over
// adjacent m-rows (bitwise == two scalar FFMAs; validated R8/R9).
// Tile 64m x 64n x 16k, 256 threads, register double-buffered global loads.
__global__ void __launch_bounds__(256) gemm_k(const float* __restrict__ A,
                                              const float* __restrict__ Bm,
                                              float* __restrict__ P,
                                              int M, int N, int K) {
    __shared__ float As[16][68];
    __shared__ float Bs[16][68];

    const int bn0 = blockIdx.x * 64, bm0 = blockIdx.y * 64;
    const int k0 = blockIdx.z * KC;
    const int kchunk = min(KC, K - k0);
    const int tid = threadIdx.x;
    const int tx = tid & 31, ty = tid >> 5;      // 32 n-groups, 8 m-groups

    const float* Ag = A + (size_t)bm0 * K + k0;
    const float* Bg = Bm + (size_t)bn0 * K + k0;

    unsigned long long acc2[4][2];               // 4 row-pairs x 2 cols
    #pragma unroll
    for (int p = 0; p < 4; p++) { acc2[p][0] = 0ull; acc2[p][1] = 0ull; }

    const int arow = tid >> 2, akq = (tid & 3) * 4;
    float4 ra = *(const float4*)(Ag + (size_t)arow * K + akq);
    float4 rb = *(const float4*)(Bg + (size_t)arow * K + akq);

    for (int kt = 0; kt < kchunk; kt += 16) {
        As[akq + 0][arow] = ra.x; As[akq + 1][arow] = ra.y;
        As[akq + 2][arow] = ra.z; As[akq + 3][arow] = ra.w;
        Bs[akq + 0][arow] = rb.x; Bs[akq + 1][arow] = rb.y;
        Bs[akq + 2][arow] = rb.z; Bs[akq + 3][arow] = rb.w;
        __syncthreads();
        int kn = kt + 16;
        if (kn < kchunk) {   // prefetch next tile during compute
            ra = *(const float4*)(Ag + (size_t)arow * K + kn + akq);
            rb = *(const float4*)(Bg + (size_t)arow * K + kn + akq);
        }
        #pragma unroll
        for (int k = 0; k < 16; k++) {
            float2 b = *(const float2*)&Bs[k][tx * 2];
            unsigned long long bb0 = f2pack(b.x, b.x);
            unsigned long long bb1 = f2pack(b.y, b.y);
            const ulonglong2* ap = (const ulonglong2*)&As[k][ty * 8];
            ulonglong2 a01 = ap[0];
            ulonglong2 a23 = ap[1];
            f2fma(acc2[0][0], a01.x, bb0); f2fma(acc2[0][1], a01.x, bb1);
            f2fma(acc2[1][0], a01.y, bb0); f2fma(acc2[1][1], a01.y, bb1);
            f2fma(acc2[2][0], a23.x, bb0); f2fma(acc2[2][1], a23.x, bb1);
            f2fma(acc2[3][0], a23.y, bb0); f2fma(acc2[3][1], a23.y, bb1);
        }
        __syncthreads();
    }
    float* Pg = P + (size_t)blockIdx.z * M * N + (size_t)bm0 * N + bn0;
    #pragma unroll
    for (int p = 0; p < 4; p++) {
        float r0c0, r1c0, r0c1, r1c1;
        f2unpack(r0c0, r1c0, acc2[p][0]);
        f2unpack(r0c1, r1c1, acc2[p][1]);
        *(float2*)&Pg[(size_t)(ty * 8 + 2 * p) * N + tx * 2] =
            make_float2(r0c0, r0c1);
        *(float2*)&Pg[(size_t)(ty * 8 + 2 * p + 1) * N + tx * 2] =
            make_float2(r1c0, r1c1);
    }
}

// ------------------------------- LIF scan ----------------------------------
// One thread per (b, n): carries V/ls in registers across all T steps.
// part layout: [S panels][tstride per step (or 0 if time-invariant)] + i.
// Panel combine: ordered fadd chain from 0 (bitwise == R7's tot).
__global__ void lifscan_k(const float* __restrict__ part, int S,
                          size_t pstride, size_t tstride,
                          const float* __restrict__ cn,
                          const float* __restrict__ tn,
                          const float* __restrict__ th,
                          const float* __restrict__ wn,
                          float* __restrict__ sall,
                          float* __restrict__ out,
                          int N) {
    int i = blockIdx.x * 256 + threadIdx.x;
    int n = i % N;
    size_t sz = (size_t)BSZ * N;
    float wnv = wn[n], thb = th[n];
    float sc = __fmul_rn(0.05f, wnv);

    float curbase = 0.f;
    if (tstride == 0) {
        curbase = __fadd_rn(0.f, part[i]);
        for (int s = 1; s < S; s++)
            curbase = __fadd_rn(curbase, part[(size_t)s * pstride + i]);
    }

    float V = 0.f, ls = -1e9f;
    float costs = 0.f;
    unsigned int cnt = 0u;

    for (int t = 1; t <= TT; t++) {
        size_t off = (size_t)(t - 1) * sz + i;
        float cur;
        if (tstride == 0) {
            cur = curbase;
        } else {
            const float* p = part + (size_t)(t - 1) * tstride + i;
            cur = __fadd_rn(0.f, p[0]);
            for (int s = 1; s < S; s++)
                cur = __fadd_rn(cur, p[(size_t)s * pstride]);
        }
        float tf = (float)t;
        cur = __fmaf_rn(cn[off], sc, cur);
        bool refrac = __fadd_rn(tf, -ls) < 2.0f;
        float Vcand = __fmaf_rn(0.95f, V, cur);
        float Vn = refrac ? V : Vcand;
        float thr = __fmaf_rn(tn[off], 0.1f, thb);
        bool sp = (!refrac) && (Vn > thr);
        V = sp ? 0.f : Vn;
        ls = sp ? tf : ls;
        float spf = sp ? 1.f : 0.f;
        if (sall) sall[off] = spf;
        if (out && t == TT) out[i] = spf;
        if (sp) {
            float cf = 0.01f * fminf(10.f, 17.f - tf);
            costs = __fadd_rn(costs, __fmul_rn(cf, wnv));
            cnt++;
        }
    }

    // block reduce cost & spike count, one atomic per block
    #pragma unroll
    for (int off = 16; off; off >>= 1) {
        costs += __shfl_down_sync(0xffffffffu, costs, off);
        cnt += __shfl_down_sync(0xffffffffu, cnt, off);
    }
    __shared__ float shc[8];
    __shared__ unsigned int shs[8];
    if ((threadIdx.x & 31) == 0) { shc[threadIdx.x >> 5] = costs; shs[threadIdx.x >> 5] = cnt; }
    __syncthreads();
    if (threadIdx.x == 0) {
        float tc = 0.f; unsigned int ts = 0u;
        #pragma unroll
        for (int k = 0; k < 8; k++) { tc += shc[k]; ts += shs[k]; }
        atomicAdd(&g_cost, (double)tc);
        atomicAdd(&g_tot, ts);
    }
}

// ------------------------------- finalize -----------------------------------
__global__ void final_k(float* out, int out_size) {
    float cost = (float)g_cost;
    float p1 = __fdiv_rn((float)g_tot, 14680064.f);
    float p0 = __fadd_rn(1.f, -p1);
    float ent = -(p1 * log2f(p1 + 1e-12f) + p0 * log2f(p0 + 1e-12f));
    if (out_size >= BSZ * N3 + 2) {
        out[BSZ * N3] = cost;
        out[BSZ * N3 + 1] = ent;
    } else if (out_size >= 2) {
        out[out_size - 2] = cost;
        out[out_size - 1] = ent;
    }
}

// ------------------------------- launch -------------------------------------
extern "C" void kernel_launch(void* const* d_in, const int* in_sizes, int n_in,
                              void* d_out, int out_size) {
    const float *inputs, *w0, *w1, *w2, *th0, *th1, *th2;
    const float *cn0, *cn1, *cn2, *tn0, *tn1, *tn2;
    inputs = (const float*)d_in[0];
    if (in_sizes[2] == 2048) {
        // interleaved (setup_inputs dict order)
        w0 = (const float*)d_in[1];  th0 = (const float*)d_in[2];
        cn0 = (const float*)d_in[3]; tn0 = (const float*)d_in[4];
        w1 = (const float*)d_in[5];  th1 = (const float*)d_in[6];
        cn1 = (const float*)d_in[7]; tn1 = (const float*)d_in[8];
        w2 = (const float*)d_in[9];  th2 = (const float*)d_in[10];
        cn2 = (const float*)d_in[11]; tn2 = (const float*)d_in[12];
    } else {
        w0 = (const float*)d_in[1];  w1 = (const float*)d_in[2];  w2 = (const float*)d_in[3];
        th0 = (const float*)d_in[4]; th1 = (const float*)d_in[5]; th2 = (const float*)d_in[6];
        cn0 = (const float*)d_in[7]; cn1 = (const float*)d_in[8]; cn2 = (const float*)d_in[9];
        tn0 = (const float*)d_in[10]; tn1 = (const float*)d_in[11]; tn2 = (const float*)d_in[12];
    }
    float* out = (float*)d_out;

    void *pI0p, *ps0, *pp1, *ps1, *pp2, *pwn0, *pwn1, *pwn2;
    cudaGetSymbolAddress(&pI0p, g_I0p);
    cudaGetSymbolAddress(&ps0, g_s0);
    cudaGetSymbolAddress(&pp1, g_p1);
    cudaGetSymbolAddress(&ps1, g_s1);
    cudaGetSymbolAddress(&pp2, g_p2);
    cudaGetSymbolAddress(&pwn0, g_wn0);
    cudaGetSymbolAddress(&pwn1, g_wn1);
    cudaGetSymbolAddress(&pwn2, g_wn2);

    const int NP1 = (N0 + KC - 1) / KC;  // 4 panels (K=1024)
    const int NP2 = (N1 + KC - 1) / KC;  // 7 panels (K=2048)

    init_k<<<1, 32>>>();
    wnorm_k<<<N1 / 8, 256>>>(w0, N0, N1, (float*)pwn0);
    wnorm_k<<<N2 / 8, 256>>>(w1, N1, N2, (float*)pwn1);
    wnorm_k<<<N3 / 8, 256>>>(w2, N2, N3, (float*)pwn2);

    // I0 = inputs @ w0^T (panel partials; combined inside lifscan)
    gemm_k<<<dim3(N1 / 64, BSZ / 64, NP1), 256>>>(inputs, w0, (float*)pI0p,
                                                  BSZ, N1, N0);

    // Layer 0 scan: all 16 steps in one launch (I0 time-invariant)
    lifscan_k<<<BSZ * N1 / 256, 256>>>((const float*)pI0p, NP1,
                                       (size_t)BSZ * N1, 0,
                                       cn0, tn0, th0, (const float*)pwn0,
                                       (float*)ps0, nullptr, N1);

    // Layer 1: one batched GEMM over all steps (M = 4096)
    gemm_k<<<dim3(N2 / 64, MB / 64, NP2), 256>>>((const float*)ps0, w1,
                                                 (float*)pp1, MB, N2, N1);
    lifscan_k<<<BSZ * N2 / 256, 256>>>((const float*)pp1, NP2,
                                       (size_t)MB * N2, (size_t)BSZ * N2,
                                       cn1, tn1, th1, (const float*)pwn1,
                                       (float*)ps1, nullptr, N2);

    // Layer 2: one batched GEMM over all steps
    gemm_k<<<dim3(N3 / 64, MB / 64, NP1), 256>>>((const float*)ps1, w2,
                                                 (float*)pp2, MB, N3, N2);
    lifscan_k<<<BSZ * N3 / 256, 256>>>((const float*)pp2, NP1,
                                       (size_t)MB * N3, (size_t)BSZ * N3,
                                       cn2, tn2, th2, (const float*)pwn2,
                                       nullptr, out, N3);

    final_k<<<1, 1>>>(out, out_size);
}